// round 2
// baseline (speedup 1.0000x reference)
#include <cuda_runtime.h>

// PowerLinear: y_b = R @ ( P_b @ (colsum(R) * x_b) )
//   P_b v = (sum v) * ones       if n_b == 0   (elementwise 0^0 = 1!)
//   P_b v = d^{n_b} * v          if n_b >= 1
//
// Inputs (metadata order): x [64,1024] f32, n [64] i32, diag [1024] f32, rot [1024,1024] f32
// Output: [64,1024] f32

#define BB 64
#define DD 1024
#define KSPLIT 8
#define KCHUNK (DD / KSPLIT)   // 128
#define KC 16                  // k-depth per smem stage
#define NSTAGE (KCHUNK / KC)   // 8
#define NTILE 64
#define PAD 68

// scratch (device globals -- no allocation allowed)
__device__ float g_cpart[KSPLIT * DD];       // column-sum partials of R
__device__ float g_M[BB * DD];               // w vectors (GEMM A operand)
__device__ float g_part2[KSPLIT * BB * DD];  // GEMM split-K partials

// ---------------------------------------------------------------------------
// K1: partial column sums of R.  grid (16, 8), 256 threads.
// block (bx,by): cols [bx*64, +64), rows [by*128, +128)
// ---------------------------------------------------------------------------
__global__ __launch_bounds__(256) void colsum_kernel(const float* __restrict__ R)
{
    const int col0 = blockIdx.x * 64;
    const int r0   = blockIdx.y * 128;
    const int tid  = threadIdx.x;
    const int tcol = tid & 63;
    const int trow = tid >> 6;          // 0..3

    float s = 0.f;
#pragma unroll
    for (int m = 0; m < 32; m++)
        s += R[(r0 + trow + 4 * m) * DD + col0 + tcol];

    __shared__ float red[4][64];
    red[trow][tcol] = s;
    __syncthreads();
    if (trow == 0) {
        float c = red[0][tcol] + red[1][tcol] + red[2][tcol] + red[3][tcol];
        g_cpart[blockIdx.y * DD + col0 + tcol] = c;
    }
}

// ---------------------------------------------------------------------------
// K2: per-batch elementwise: z = c*x_b ; w = (n==0) ? sum(z) : d^n * z
// grid 64 (one block per batch row), 256 threads.
// ---------------------------------------------------------------------------
__global__ __launch_bounds__(256) void middle_kernel(const float* __restrict__ x,
                                                     const int*   __restrict__ n,
                                                     const float* __restrict__ diag)
{
    const int b   = blockIdx.x;
    const int tid = threadIdx.x;
    const int nb  = n[b];

    float z[4];
    float local = 0.f;
#pragma unroll
    for (int v = 0; v < 4; v++) {
        const int j = v * 256 + tid;
        float c = 0.f;
#pragma unroll
        for (int p = 0; p < KSPLIT; p++) c += g_cpart[p * DD + j];
        z[v] = c * x[b * DD + j];
        local += z[v];
    }

    __shared__ float red[256];
    red[tid] = local;
    __syncthreads();
#pragma unroll
    for (int off = 128; off > 0; off >>= 1) {
        if (tid < off) red[tid] += red[tid + off];
        __syncthreads();
    }
    const float rowsum = red[0];

#pragma unroll
    for (int v = 0; v < 4; v++) {
        const int j = v * 256 + tid;
        const float d = diag[j];
        float p = 1.f;
#pragma unroll
        for (int k = 0; k < 5; k++) p *= (k < nb) ? d : 1.f;  // d^nb, nb in [0,5]
        g_M[b * DD + j] = (nb == 0) ? rowsum : z[v] * p;
    }
}

// ---------------------------------------------------------------------------
// K3: split-K GEMM:  Ypart[ks][b][i] = sum_{j in chunk ks} M[b][j] * R[i][j]
// grid (16 col-tiles, 8 k-splits), 256 threads.
// Block tile: 64(b) x 64(i), K chunk = 128, 4x4 register microtile/thread.
// Double-buffered smem, float4 global loads, R loaded transposed into smem.
// ---------------------------------------------------------------------------
__global__ __launch_bounds__(256, 1) void gemm_kernel(const float* __restrict__ R)
{
    __shared__ __align__(16) float sA[2][KC][PAD];  // sA[k][b] = M[b][k0+k]
    __shared__ __align__(16) float sB[2][KC][PAD];  // sB[k][i] = R[col0+i][k0+k]

    const int col0 = blockIdx.x * NTILE;
    const int k0   = blockIdx.y * KCHUNK;
    const int tid  = threadIdx.x;
    const int tx   = tid & 15;
    const int ty   = tid >> 4;

    // loader indices (shared by A and transposed-B loads)
    const int lb = tid >> 2;          // 0..63
    const int lk = (tid & 3) * 4;     // 0,4,8,12

    float acc[4][4];
#pragma unroll
    for (int r = 0; r < 4; r++)
#pragma unroll
        for (int c = 0; c < 4; c++) acc[r][c] = 0.f;

    float4 ra = *(const float4*)(g_M + lb * DD + k0 + lk);
    float4 rb = *(const float4*)(R + (col0 + lb) * DD + k0 + lk);

    int buf = 0;
#pragma unroll
    for (int s = 0; s < NSTAGE; s++) {
        sA[buf][lk + 0][lb] = ra.x;
        sA[buf][lk + 1][lb] = ra.y;
        sA[buf][lk + 2][lb] = ra.z;
        sA[buf][lk + 3][lb] = ra.w;
        sB[buf][lk + 0][lb] = rb.x;
        sB[buf][lk + 1][lb] = rb.y;
        sB[buf][lk + 2][lb] = rb.z;
        sB[buf][lk + 3][lb] = rb.w;
        __syncthreads();

        if (s + 1 < NSTAGE) {
            const int kb = k0 + (s + 1) * KC;
            ra = *(const float4*)(g_M + lb * DD + kb + lk);
            rb = *(const float4*)(R + (col0 + lb) * DD + kb + lk);
        }

#pragma unroll
        for (int kk = 0; kk < KC; kk++) {
            const float4 av = *(const float4*)&sA[buf][kk][ty * 4];
            const float4 bv = *(const float4*)&sB[buf][kk][tx * 4];
            acc[0][0] = fmaf(av.x, bv.x, acc[0][0]);
            acc[0][1] = fmaf(av.x, bv.y, acc[0][1]);
            acc[0][2] = fmaf(av.x, bv.z, acc[0][2]);
            acc[0][3] = fmaf(av.x, bv.w, acc[0][3]);
            acc[1][0] = fmaf(av.y, bv.x, acc[1][0]);
            acc[1][1] = fmaf(av.y, bv.y, acc[1][1]);
            acc[1][2] = fmaf(av.y, bv.z, acc[1][2]);
            acc[1][3] = fmaf(av.y, bv.w, acc[1][3]);
            acc[2][0] = fmaf(av.z, bv.x, acc[2][0]);
            acc[2][1] = fmaf(av.z, bv.y, acc[2][1]);
            acc[2][2] = fmaf(av.z, bv.z, acc[2][2]);
            acc[2][3] = fmaf(av.z, bv.w, acc[2][3]);
            acc[3][0] = fmaf(av.w, bv.x, acc[3][0]);
            acc[3][1] = fmaf(av.w, bv.y, acc[3][1]);
            acc[3][2] = fmaf(av.w, bv.z, acc[3][2]);
            acc[3][3] = fmaf(av.w, bv.w, acc[3][3]);
        }
        buf ^= 1;
    }

    float* o = g_part2 + blockIdx.y * (BB * DD);
#pragma unroll
    for (int r = 0; r < 4; r++) {
        float4 v = make_float4(acc[r][0], acc[r][1], acc[r][2], acc[r][3]);
        *(float4*)(o + (ty * 4 + r) * DD + col0 + tx * 4) = v;
    }
}

// ---------------------------------------------------------------------------
// K4: sum split-K partials -> d_out. grid 256, 256 threads.
// ---------------------------------------------------------------------------
__global__ __launch_bounds__(256) void final_kernel(float* __restrict__ out)
{
    const int idx = blockIdx.x * 256 + threadIdx.x;
    float s = 0.f;
#pragma unroll
    for (int p = 0; p < KSPLIT; p++) s += g_part2[p * (BB * DD) + idx];
    out[idx] = s;
}

// ---------------------------------------------------------------------------
extern "C" void kernel_launch(void* const* d_in, const int* in_sizes, int n_in,
                              void* d_out, int out_size)
{
    const float* x    = (const float*)d_in[0];
    const int*   n    = (const int*)  d_in[1];
    const float* diag = (const float*)d_in[2];
    const float* rot  = (const float*)d_in[3];
    float* out = (float*)d_out;

    colsum_kernel<<<dim3(16, KSPLIT), 256>>>(rot);
    middle_kernel<<<64, 256>>>(x, n, diag);
    gemm_kernel<<<dim3(DD / NTILE, KSPLIT), 256>>>(rot);
    final_kernel<<<(BB * DD) / 256, 256>>>(out);
}